// round 12
// baseline (speedup 1.0000x reference)
#include <cuda_runtime.h>
#include <cuda_fp16.h>

#define TILE 128
#define NT_MAX 64
#define MAX_BLOCKS (NT_MAX * (NT_MAX + 1) / 2)   // 2080 for N=8192

// Per-block partial sums + completion counter (no allocations, deterministic).
__device__ double g_partials[MAX_BLOCKS];
__device__ int    g_count = 0;

static __device__ __forceinline__ float lg2_approx(float x) {
    float r; asm("lg2.approx.f32 %0, %1;" : "=f"(r) : "f"(x)); return r;
}
static __device__ __forceinline__ float rcp_approx(float x) {
    float r; asm("rcp.approx.f32 %0, %1;" : "=f"(r) : "f"(x)); return r;
}
// Dual exp2: one MUFU warp-instruction for two values.
static __device__ __forceinline__ __half2 h2ex2(__half2 x) {
    unsigned in = *reinterpret_cast<unsigned*>(&x), out;
    asm("ex2.approx.f16x2 %0, %1;" : "=r"(out) : "r"(in));
    return *reinterpret_cast<__half2*>(&out);
}
// 1/x for x in [1, ~2^15]: bit-magic seed (~3.4% err) + 2 Newton steps (~1e-6).
// 1 alu + 4 fma-pipe ops; independent of the EX2/LG2 chain (ILP).
static __device__ __forceinline__ float fast_rcp(float x) {
    float y = __int_as_float(0x7EF311C2 - __float_as_int(x));
    y = y * fmaf(-x, y, 2.0f);
    y = y * fmaf(-x, y, 2.0f);
    return y;
}

#define LOG2E 1.44269504088896340f
#define LN2_D 0.6931471805599453094  // double, applied once at the end

__global__ void __launch_bounds__(TILE)
wrnl_kernel(const float* __restrict__ logits,
            const int* __restrict__ rankings,   // JAX x64 disabled -> int32
            float* __restrict__ out,
            int n, int nt, int nblocks) {
    const int t = threadIdx.x;

    // ---- decode triangular block index k -> (ti, tj), ti <= tj ----
    const int k = blockIdx.x;
    float bb = 2.0f * (float)nt + 1.0f;
    int ti = (int)((bb - sqrtf(bb * bb - 8.0f * (float)k)) * 0.5f);
    while (ti > 0 && k < ti * nt - (ti * (ti - 1)) / 2) --ti;
    while (k >= (ti + 1) * nt - ((ti + 1) * ti) / 2) ++ti;
    const int tj = ti + (k - (ti * nt - (ti * (ti - 1)) / 2));

    // j-tile, one float4 per j-pair: {.x = half2(x_{2b}, x_{2b+1}) bits,
    //                                 .y = r_{2b}, .z = r_{2b+1}, .w = unused}
    // where x_j = logit_j * log2e. One LDS.128 per 2 pairs.
    __shared__ float4 sJ[TILE / 2];

    const int gi = ti * TILE + t;
    const int gj = tj * TILE + t;

    float lip, ri;                       // li pre-scaled by log2e; rank as float
    if (gi < n) { lip = logits[gi] * LOG2E; ri = (float)rankings[gi]; }
    else        { lip = 0.0f;               ri = 3.0e9f; }    // never active
    {
        float xj, rj;
        if (gj < n) { xj = logits[gj] * LOG2E; rj = (float)rankings[gj]; }
        else        { xj = 0.0f;               rj = -1.0f; }  // inactive
        const int b   = t >> 1;
        const int sub = t & 1;
        // disjoint 2-byte / 4-byte stores within the float4 -> no race
        ((__half*)&sJ[b])[sub] = __float2half_rn(xj);   // bytes [0..3] of .x
        (&sJ[b].y)[sub] = rj;                           // .y or .z
        if (sub) sJ[b].w = 0.0f;                        // keep .w defined
    }
    __syncthreads();

    const __half2 lip2 = __float2half2_rn(lip);

    float acc0 = 0.0f, acc1 = 0.0f;

    if (ti != tj) {
        // off-diagonal: i<j holds globally; only the rank test gates a pair
        #pragma unroll 16
        for (int b = 0; b < TILE / 2; ++b) {
            float4 q = sJ[b];                     // LDS.128 broadcast
            __half2 xq = *reinterpret_cast<__half2*>(&q.x);
            __half2 xh = __hsub2(xq, lip2);       // both x's, one HADD2-class op
            __half2 eh = h2ex2(xh);               // both exp2's, one MUFU
            float e0 = __low2float(eh);           // F2F
            float e1 = __high2float(eh);          // F2F
            float g0 = lg2_approx(1.0f + e0);     // FADD + MUFU.LG2
            float g1 = lg2_approx(1.0f + e1);
            float w0 = rcp_approx(ri + q.y);      // FADD + MUFU.RCP   (pair 0)
            float w1 = fast_rcp(ri + q.z);        // fma-pipe Newton   (pair 1)
            if (ri < q.y) acc0 = fmaf(g0, w0, acc0);
            if (ri < q.z) acc1 = fmaf(g1, w1, acc1);
        }
    } else {
        // diagonal tile: additionally require t < j (j = 2b, 2b+1)
        #pragma unroll 16
        for (int b = 0; b < TILE / 2; ++b) {
            float4 q = sJ[b];
            __half2 xq = *reinterpret_cast<__half2*>(&q.x);
            __half2 xh = __hsub2(xq, lip2);
            __half2 eh = h2ex2(xh);
            float e0 = __low2float(eh);
            float e1 = __high2float(eh);
            float g0 = lg2_approx(1.0f + e0);
            float g1 = lg2_approx(1.0f + e1);
            float w0 = rcp_approx(ri + q.y);
            float w1 = fast_rcp(ri + q.z);
            int jj = 2 * b;
            if ((ri < q.y) && (t < jj))     acc0 = fmaf(g0, w0, acc0);
            if ((ri < q.z) && (t < jj + 1)) acc1 = fmaf(g1, w1, acc1);
        }
    }

    // ---- block reduction to one double partial ----
    float acc = acc0 + acc1;
    #pragma unroll
    for (int off = 16; off > 0; off >>= 1)
        acc += __shfl_down_sync(0xffffffffu, acc, off);

    __shared__ float warpSum[4];
    __shared__ bool  isLast;
    if ((t & 31) == 0) warpSum[t >> 5] = acc;
    __syncthreads();
    if (t == 0) {
        double s = (double)warpSum[0] + (double)warpSum[1]
                 + (double)warpSum[2] + (double)warpSum[3];
        g_partials[k] = s;
        __threadfence();
        int old = atomicAdd(&g_count, 1);
        isLast = (old == nblocks - 1);
    }
    __syncthreads();
    if (!isLast) return;

    // ---- last block: deterministic final reduction ----
    __threadfence();
    double a = 0.0;
    for (int i = t; i < nblocks; i += TILE) a += g_partials[i];
    #pragma unroll
    for (int off = 16; off > 0; off >>= 1)
        a += __shfl_down_sync(0xffffffffu, a, off);

    __shared__ double ws2[4];
    if ((t & 31) == 0) ws2[t >> 5] = a;
    __syncthreads();
    if (t == 0) {
        double s = ws2[0] + ws2[1] + ws2[2] + ws2[3];
        out[0] = (float)(s * LN2_D / (double)n);   // ln2 hoisted out of the whole sum
        g_count = 0;                               // reset for next graph replay
    }
}

extern "C" void kernel_launch(void* const* d_in, const int* in_sizes, int n_in,
                              void* d_out, int out_size) {
    const float* logits   = (const float*)d_in[0];
    const int*   rankings = (const int*)d_in[1];
    int n  = in_sizes[0];
    int nt = (n + TILE - 1) / TILE;          // 64 for N=8192
    int nblocks = nt * (nt + 1) / 2;         // 2080

    wrnl_kernel<<<nblocks, TILE>>>(logits, rankings, (float*)d_out, n, nt, nblocks);
}

// round 13
// speedup vs baseline: 1.0707x; 1.0707x over previous
#include <cuda_runtime.h>

#define BI 256            // i-rows per block (2 per thread)
#define BJ 128            // j-cols per block
#define THREADS 128
#define MAX_BLOCKS 2080   // >= 1056 needed for N=8192

// Per-block partial sums + completion counter (no allocations, deterministic).
__device__ double g_partials[MAX_BLOCKS];
__device__ int    g_count = 0;

static __device__ __forceinline__ float ex2_approx(float x) {
    float r; asm("ex2.approx.f32 %0, %1;" : "=f"(r) : "f"(x)); return r;
}
static __device__ __forceinline__ float lg2_approx(float x) {
    float r; asm("lg2.approx.f32 %0, %1;" : "=f"(r) : "f"(x)); return r;
}
// 1/x for x in [1, ~2^15]: bit-magic seed (~3.4% err) + 2 Newton steps (~1e-6).
// 1 alu + 4 fma-pipe ops; keeps the XU pipe free for EX2/LG2.
static __device__ __forceinline__ float fast_rcp(float x) {
    float y = __int_as_float(0x7EF311C2 - __float_as_int(x));
    y = y * fmaf(-x, y, 2.0f);
    y = y * fmaf(-x, y, 2.0f);
    return y;
}

#define LOG2E 1.44269504088896340f
#define LN2_D 0.6931471805599453094  // double, applied once at the end

__global__ void __launch_bounds__(THREADS)
wrnl_kernel(const float* __restrict__ logits,
            const int* __restrict__ rankings,   // JAX x64 disabled -> int32
            float* __restrict__ out,
            int n, int ntj, int nblocks) {
    const int t = threadIdx.x;
    const int k = blockIdx.x;

    // ---- decode block index k -> (ti, tj): ti over 256-row i-blocks,
    //      tj over 128-col j-blocks, tj >= 2*ti (blocks with any i<j work).
    //      off(ti) = ti*ntj - ti*(ti-1)
    float c = (float)(ntj + 1);
    int ti = (int)((c - sqrtf(c * c - 4.0f * (float)k)) * 0.5f);
    while (ti > 0 && k < ti * ntj - ti * (ti - 1)) --ti;
    while (k >= (ti + 1) * ntj - (ti + 1) * ti) ++ti;
    const int tj = 2 * ti + (k - (ti * ntj - ti * (ti - 1)));
    const bool masked = (tj <= 2 * ti + 1);    // j-range overlaps i-range

    // j-tile, float4 per 2 j's: {x_{2b}, r_{2b}, x_{2b+1}, r_{2b+1}},
    // x_j = logit_j * log2e (f32). One LDS.128 serves 4 pairs.
    __shared__ float4 sJ[BJ / 2];

    // each thread owns two i-rows: gi0 = base+t, gi1 = base+t+128
    const int gi0 = ti * BI + t;
    const int gi1 = gi0 + 128;
    float x0, r0, x1, r1;
    if (gi0 < n) { x0 = logits[gi0] * LOG2E; r0 = (float)rankings[gi0]; }
    else         { x0 = 0.0f;                r0 = 3.0e9f; }   // never active
    if (gi1 < n) { x1 = logits[gi1] * LOG2E; r1 = (float)rankings[gi1]; }
    else         { x1 = 0.0f;                r1 = 3.0e9f; }

    {
        const int gj = tj * BJ + t;
        float xj, rj;
        if (gj < n) { xj = logits[gj] * LOG2E; rj = (float)rankings[gj]; }
        else        { xj = 0.0f;               rj = -1.0f; }  // inactive
        ((float2*)sJ)[t] = make_float2(xj, rj);
    }
    __syncthreads();

    float a00 = 0.0f, a01 = 0.0f, a10 = 0.0f, a11 = 0.0f;

    if (!masked) {
        // fully interior: every (i,j) here has i<j; only the rank test gates
        #pragma unroll 8
        for (int b = 0; b < BJ / 2; ++b) {
            float4 q = sJ[b];                        // LDS.128 broadcast
            // (i0, j0)
            float e00 = ex2_approx(q.x - x0);
            float g00 = lg2_approx(1.0f + e00);
            float w00 = fast_rcp(r0 + q.y);
            if (r0 < q.y) a00 = fmaf(g00, w00, a00);
            // (i0, j1)
            float e01 = ex2_approx(q.z - x0);
            float g01 = lg2_approx(1.0f + e01);
            float w01 = fast_rcp(r0 + q.w);
            if (r0 < q.w) a01 = fmaf(g01, w01, a01);
            // (i1, j0)
            float e10 = ex2_approx(q.x - x1);
            float g10 = lg2_approx(1.0f + e10);
            float w10 = fast_rcp(r1 + q.y);
            if (r1 < q.y) a10 = fmaf(g10, w10, a10);
            // (i1, j1)
            float e11 = ex2_approx(q.z - x1);
            float g11 = lg2_approx(1.0f + e11);
            float w11 = fast_rcp(r1 + q.w);
            if (r1 < q.w) a11 = fmaf(g11, w11, a11);
        }
    } else {
        // boundary blocks (tj = 2ti or 2ti+1): additionally require gi < gj
        const int j0base = tj * BJ;
        #pragma unroll 8
        for (int b = 0; b < BJ / 2; ++b) {
            float4 q = sJ[b];
            int gj0 = j0base + 2 * b;
            int gj1 = gj0 + 1;
            float e00 = ex2_approx(q.x - x0);
            float g00 = lg2_approx(1.0f + e00);
            float w00 = fast_rcp(r0 + q.y);
            if ((r0 < q.y) && (gi0 < gj0)) a00 = fmaf(g00, w00, a00);
            float e01 = ex2_approx(q.z - x0);
            float g01 = lg2_approx(1.0f + e01);
            float w01 = fast_rcp(r0 + q.w);
            if ((r0 < q.w) && (gi0 < gj1)) a01 = fmaf(g01, w01, a01);
            float e10 = ex2_approx(q.x - x1);
            float g10 = lg2_approx(1.0f + e10);
            float w10 = fast_rcp(r1 + q.y);
            if ((r1 < q.y) && (gi1 < gj0)) a10 = fmaf(g10, w10, a10);
            float e11 = ex2_approx(q.z - x1);
            float g11 = lg2_approx(1.0f + e11);
            float w11 = fast_rcp(r1 + q.w);
            if ((r1 < q.w) && (gi1 < gj1)) a11 = fmaf(g11, w11, a11);
        }
    }

    // ---- block reduction to one double partial ----
    float acc = (a00 + a01) + (a10 + a11);
    #pragma unroll
    for (int off = 16; off > 0; off >>= 1)
        acc += __shfl_down_sync(0xffffffffu, acc, off);

    __shared__ float warpSum[4];
    __shared__ bool  isLast;
    if ((t & 31) == 0) warpSum[t >> 5] = acc;
    __syncthreads();
    if (t == 0) {
        double s = (double)warpSum[0] + (double)warpSum[1]
                 + (double)warpSum[2] + (double)warpSum[3];
        g_partials[k] = s;
        __threadfence();
        int old = atomicAdd(&g_count, 1);
        isLast = (old == nblocks - 1);
    }
    __syncthreads();
    if (!isLast) return;

    // ---- last block: deterministic final reduction ----
    __threadfence();
    double a = 0.0;
    for (int i = t; i < nblocks; i += THREADS) a += g_partials[i];
    #pragma unroll
    for (int off = 16; off > 0; off >>= 1)
        a += __shfl_down_sync(0xffffffffu, a, off);

    __shared__ double ws2[4];
    if ((t & 31) == 0) ws2[t >> 5] = a;
    __syncthreads();
    if (t == 0) {
        double s = ws2[0] + ws2[1] + ws2[2] + ws2[3];
        out[0] = (float)(s * LN2_D / (double)n);   // ln2 hoisted out of the whole sum
        g_count = 0;                               // reset for next graph replay
    }
}

extern "C" void kernel_launch(void* const* d_in, const int* in_sizes, int n_in,
                              void* d_out, int out_size) {
    const float* logits   = (const float*)d_in[0];
    const int*   rankings = (const int*)d_in[1];
    int n   = in_sizes[0];
    int nti = (n + BI - 1) / BI;             // 32 for N=8192
    int ntj = (n + BJ - 1) / BJ;             // 64 for N=8192

    // blocks: for each ti, tj runs [2*ti, ntj)
    int nblocks = 0;
    for (int ti = 0; ti < nti; ++ti) {
        int cnt = ntj - 2 * ti;
        if (cnt > 0) nblocks += cnt;
    }
    // == 1056 for N=8192

    wrnl_kernel<<<nblocks, THREADS>>>(logits, rankings, (float*)d_out, n, ntj, nblocks);
}

// round 14
// speedup vs baseline: 1.1429x; 1.0674x over previous
#include <cuda_runtime.h>

#define BI 256            // i-rows per block (2 per thread)
#define BJ 128            // j-cols per block
#define THREADS 128
#define MAX_BLOCKS 2080   // >= 1056 needed for N=8192

// Per-block partial sums + completion counter (no allocations, deterministic).
__device__ double g_partials[MAX_BLOCKS];
__device__ int    g_count = 0;

static __device__ __forceinline__ float ex2_approx(float x) {
    float r; asm("ex2.approx.f32 %0, %1;" : "=f"(r) : "f"(x)); return r;
}
static __device__ __forceinline__ float lg2_approx(float x) {
    float r; asm("lg2.approx.f32 %0, %1;" : "=f"(r) : "f"(x)); return r;
}
// 1/x for x in [1, ~2^15]: bit-magic seed (~3.4% err) + 2 Newton steps (~1e-6).
// 1 alu + 4 fma-pipe ops; keeps the XU pipe free for EX2/LG2.
static __device__ __forceinline__ float fast_rcp(float x) {
    float y = __int_as_float(0x7EF311C2 - __float_as_int(x));
    y = y * fmaf(-x, y, 2.0f);
    y = y * fmaf(-x, y, 2.0f);
    return y;
}

#define LOG2E 1.44269504088896340f
#define LN2_D 0.6931471805599453094  // double, applied once at the end

// one pair-chain: softplus(lg-space) * weight, predicated accumulate
#define PAIR(xj, rj, xi, ri_, cond, acc)                  \
    {                                                     \
        float e_ = ex2_approx((xj) - (xi));               \
        float g_ = lg2_approx(1.0f + e_);                 \
        float w_ = fast_rcp((ri_) + (rj));                \
        if (cond) acc = fmaf(g_, w_, acc);                \
    }

__global__ void __launch_bounds__(THREADS)
wrnl_kernel(const float* __restrict__ logits,
            const int* __restrict__ rankings,   // JAX x64 disabled -> int32
            float* __restrict__ out,
            int n, int ntj, int nblocks) {
    const int t = threadIdx.x;
    const int k = blockIdx.x;

    // ---- decode block index k -> (ti, tj): ti over 256-row i-blocks,
    //      tj over 128-col j-blocks, tj >= 2*ti; off(ti) = ti*ntj - ti*(ti-1)
    float c = (float)(ntj + 1);
    int ti = (int)((c - sqrtf(c * c - 4.0f * (float)k)) * 0.5f);
    while (ti > 0 && k < ti * ntj - ti * (ti - 1)) --ti;
    while (k >= (ti + 1) * ntj - (ti + 1) * ti) ++ti;
    const int tj = 2 * ti + (k - (ti * ntj - ti * (ti - 1)));
    const bool masked = (tj <= 2 * ti + 1);    // j-range overlaps i-range

    // j-tile, float4 per 2 j's: {x_{2b}, r_{2b}, x_{2b+1}, r_{2b+1}},
    // x_j = logit_j * log2e (f32).
    __shared__ float4 sJ[BJ / 2];

    // each thread owns two i-rows: gi0 = base+t, gi1 = base+t+128
    const int gi0 = ti * BI + t;
    const int gi1 = gi0 + 128;
    float x0, r0, x1, r1;
    if (gi0 < n) { x0 = logits[gi0] * LOG2E; r0 = (float)rankings[gi0]; }
    else         { x0 = 0.0f;                r0 = 3.0e9f; }   // never active
    if (gi1 < n) { x1 = logits[gi1] * LOG2E; r1 = (float)rankings[gi1]; }
    else         { x1 = 0.0f;                r1 = 3.0e9f; }

    {
        const int gj = tj * BJ + t;
        float xj, rj;
        if (gj < n) { xj = logits[gj] * LOG2E; rj = (float)rankings[gj]; }
        else        { xj = 0.0f;               rj = -1.0f; }  // inactive
        ((float2*)sJ)[t] = make_float2(xj, rj);
    }
    __syncthreads();

    float a00 = 0.0f, a01 = 0.0f, a02 = 0.0f, a03 = 0.0f;
    float a10 = 0.0f, a11 = 0.0f, a12 = 0.0f, a13 = 0.0f;

    if (!masked) {
        // fully interior: every (i,j) here has i<j; only the rank test gates.
        // 4 j's per iteration (2x LDS.128), 8 independent pair-chains.
        #pragma unroll 8
        for (int b = 0; b < BJ / 4; ++b) {
            float4 qa = sJ[2 * b];                   // j = 4b, 4b+1
            float4 qb = sJ[2 * b + 1];               // j = 4b+2, 4b+3
            PAIR(qa.x, qa.y, x0, r0, (r0 < qa.y), a00)
            PAIR(qa.z, qa.w, x0, r0, (r0 < qa.w), a01)
            PAIR(qb.x, qb.y, x0, r0, (r0 < qb.y), a02)
            PAIR(qb.z, qb.w, x0, r0, (r0 < qb.w), a03)
            PAIR(qa.x, qa.y, x1, r1, (r1 < qa.y), a10)
            PAIR(qa.z, qa.w, x1, r1, (r1 < qa.w), a11)
            PAIR(qb.x, qb.y, x1, r1, (r1 < qb.y), a12)
            PAIR(qb.z, qb.w, x1, r1, (r1 < qb.w), a13)
        }
    } else {
        // boundary blocks (tj = 2ti or 2ti+1): additionally require gi < gj
        const int j0base = tj * BJ;
        #pragma unroll 8
        for (int b = 0; b < BJ / 4; ++b) {
            float4 qa = sJ[2 * b];
            float4 qb = sJ[2 * b + 1];
            int g0 = j0base + 4 * b;
            PAIR(qa.x, qa.y, x0, r0, ((r0 < qa.y) && (gi0 < g0)),     a00)
            PAIR(qa.z, qa.w, x0, r0, ((r0 < qa.w) && (gi0 < g0 + 1)), a01)
            PAIR(qb.x, qb.y, x0, r0, ((r0 < qb.y) && (gi0 < g0 + 2)), a02)
            PAIR(qb.z, qb.w, x0, r0, ((r0 < qb.w) && (gi0 < g0 + 3)), a03)
            PAIR(qa.x, qa.y, x1, r1, ((r1 < qa.y) && (gi1 < g0)),     a10)
            PAIR(qa.z, qa.w, x1, r1, ((r1 < qa.w) && (gi1 < g0 + 1)), a11)
            PAIR(qb.x, qb.y, x1, r1, ((r1 < qb.y) && (gi1 < g0 + 2)), a12)
            PAIR(qb.z, qb.w, x1, r1, ((r1 < qb.w) && (gi1 < g0 + 3)), a13)
        }
    }

    // ---- block reduction to one double partial ----
    float acc = ((a00 + a01) + (a02 + a03)) + ((a10 + a11) + (a12 + a13));
    #pragma unroll
    for (int off = 16; off > 0; off >>= 1)
        acc += __shfl_down_sync(0xffffffffu, acc, off);

    __shared__ float warpSum[4];
    __shared__ bool  isLast;
    if ((t & 31) == 0) warpSum[t >> 5] = acc;
    __syncthreads();
    if (t == 0) {
        double s = (double)warpSum[0] + (double)warpSum[1]
                 + (double)warpSum[2] + (double)warpSum[3];
        g_partials[k] = s;
        __threadfence();
        int old = atomicAdd(&g_count, 1);
        isLast = (old == nblocks - 1);
    }
    __syncthreads();
    if (!isLast) return;

    // ---- last block: deterministic final reduction ----
    __threadfence();
    double a = 0.0;
    for (int i = t; i < nblocks; i += THREADS) a += g_partials[i];
    #pragma unroll
    for (int off = 16; off > 0; off >>= 1)
        a += __shfl_down_sync(0xffffffffu, a, off);

    __shared__ double ws2[4];
    if ((t & 31) == 0) ws2[t >> 5] = a;
    __syncthreads();
    if (t == 0) {
        double s = ws2[0] + ws2[1] + ws2[2] + ws2[3];
        out[0] = (float)(s * LN2_D / (double)n);   // ln2 hoisted out of the whole sum
        g_count = 0;                               // reset for next graph replay
    }
}

extern "C" void kernel_launch(void* const* d_in, const int* in_sizes, int n_in,
                              void* d_out, int out_size) {
    const float* logits   = (const float*)d_in[0];
    const int*   rankings = (const int*)d_in[1];
    int n   = in_sizes[0];
    int nti = (n + BI - 1) / BI;             // 32 for N=8192
    int ntj = (n + BJ - 1) / BJ;             // 64 for N=8192

    // blocks: for each ti, tj runs [2*ti, ntj)
    int nblocks = 0;
    for (int ti = 0; ti < nti; ++ti) {
        int cnt = ntj - 2 * ti;
        if (cnt > 0) nblocks += cnt;
    }
    // == 1056 for N=8192

    wrnl_kernel<<<nblocks, THREADS>>>(logits, rankings, (float*)d_out, n, ntj, nblocks);
}